// round 10
// baseline (speedup 1.0000x reference)
#include <cuda_runtime.h>
#include <cuda_bf16.h>
#include <math.h>

#define T_SEQ   2048
#define BATCH   2
#define DM      1024
#define NH      16
#define DH      64
#define MROWS   (BATCH*T_SEQ)    /* 4096 */
#define N_QKV   (3*DM)           /* 3072 */
#define KW      (DM/2)           /* 512 words per row (bf16 pairs) */

// ---------------------------------------------------------------------------
// Pre-split bf16 hi/lo storage (allocation-free rule: __device__ globals).
// word = packed bf16x2 (even element low half).
// ---------------------------------------------------------------------------
__device__ unsigned g_Xh[MROWS*KW],  g_Xl[MROWS*KW];      // X split [m][kpair]
__device__ unsigned g_Wqh[N_QKV*KW], g_Wql[N_QKV*KW];     // W_qkv^T [n][kpair]
__device__ unsigned g_Wph[DM*KW],    g_Wpl[DM*KW];        // W_proj^T [n][kpair]
__device__ unsigned g_Qh[MROWS*DM/2], g_Ql[MROWS*DM/2];   // [b,h,t][32], pre-scaled
__device__ unsigned g_Kh[MROWS*DM/2], g_Kl[MROWS*DM/2];   // [b,h,t][32]
__device__ float    g_V[MROWS*DM];                        // [b,h,t][64] fp32
__device__ unsigned g_Vth[MROWS*DM/2], g_Vtl[MROWS*DM/2]; // [b,h][d][tpair]
__device__ unsigned g_Ah[MROWS*KW],  g_Al[MROWS*KW];      // attn out split

// ---------------------------------------------------------------------------
__device__ __forceinline__ void split2(float a, float b, unsigned &hi, unsigned &lo)
{
    __nv_bfloat16 ha = __float2bfloat16_rn(a);
    __nv_bfloat16 hb = __float2bfloat16_rn(b);
    __nv_bfloat162 h; h.x = ha; h.y = hb;
    hi = *reinterpret_cast<unsigned*>(&h);
    __nv_bfloat162 l = __floats2bfloat162_rn(a - __bfloat162float(ha),
                                             b - __bfloat162float(hb));
    lo = *reinterpret_cast<unsigned*>(&l);
}

__device__ __forceinline__ void mma16816(float* d,
    unsigned a0, unsigned a1, unsigned a2, unsigned a3,
    unsigned b0, unsigned b1)
{
    asm volatile(
        "mma.sync.aligned.m16n8k16.row.col.f32.bf16.bf16.f32 "
        "{%0,%1,%2,%3}, {%4,%5,%6,%7}, {%8,%9}, {%0,%1,%2,%3};\n"
        : "+f"(d[0]), "+f"(d[1]), "+f"(d[2]), "+f"(d[3])
        : "r"(a0), "r"(a1), "r"(a2), "r"(a3), "r"(b0), "r"(b1));
}

// ---------------------------------------------------------------------------
// Prep 1: elementwise split of row-major fp32 (pairs along k). 8 floats/thread.
// ---------------------------------------------------------------------------
__global__ __launch_bounds__(256)
void split_rows_kernel(const float* __restrict__ src,
                       unsigned* __restrict__ dh, unsigned* __restrict__ dl)
{
    const int gt = blockIdx.x * 256 + threadIdx.x;
    const float4* s4 = (const float4*)src;
    float4 v0 = s4[gt * 2];
    float4 v1 = s4[gt * 2 + 1];
    unsigned h, l;
    const int o = gt * 4;
    split2(v0.x, v0.y, h, l); dh[o]     = h; dl[o]     = l;
    split2(v0.z, v0.w, h, l); dh[o + 1] = h; dl[o + 1] = l;
    split2(v1.x, v1.y, h, l); dh[o + 2] = h; dl[o + 2] = l;
    split2(v1.z, v1.w, h, l); dh[o + 3] = h; dl[o + 3] = l;
}

// ---------------------------------------------------------------------------
// Prep 2: transpose+split W[k][N] -> [n][kpair]. 64x64 tiles, 256 threads.
// ---------------------------------------------------------------------------
__global__ __launch_bounds__(256)
void wsplit_kernel(const float* __restrict__ W,
                   unsigned* __restrict__ wh, unsigned* __restrict__ wl, int N)
{
    __shared__ float sw[64][68];
    const int tid = threadIdx.x;
    const int k0 = blockIdx.x * 64;
    const int n0 = blockIdx.y * 64;

#pragma unroll
    for (int i = 0; i < 4; i++) {
        const int row = (tid >> 4) + i * 16;
        const int col = (tid & 15) * 4;
        float4 v = *(const float4*)&W[(size_t)(k0 + row) * N + n0 + col];
        *(float4*)&sw[row][col] = v;
    }
    __syncthreads();

    const int n  = tid & 63;
    const int kb = (tid >> 6) * 8;
#pragma unroll
    for (int j = 0; j < 8; j++) {
        const int kp = kb + j;
        unsigned h, l;
        split2(sw[2 * kp][n], sw[2 * kp + 1][n], h, l);
        const size_t o = (size_t)(n0 + n) * KW + (k0 >> 1) + kp;
        wh[o] = h; wl[o] = l;
    }
}

// ---------------------------------------------------------------------------
// Prep 3: V [b,h,t,d] fp32 -> transposed split [b,h][d][tpair].
// grid (T_SEQ/64, BATCH*NH), 256 threads.
// ---------------------------------------------------------------------------
__global__ __launch_bounds__(256)
void vtrans_kernel()
{
    __shared__ float sv[64][68];   // [t][d]
    const int tid = threadIdx.x;
    const int bh  = blockIdx.y;
    const int t0  = blockIdx.x * 64;

#pragma unroll
    for (int i = 0; i < 4; i++) {
        const int t = (tid >> 4) + i * 16;
        const int d = (tid & 15) * 4;
        *(float4*)&sv[t][d] =
            *(const float4*)&g_V[((size_t)bh * T_SEQ + t0 + t) * DH + d];
    }
    __syncthreads();

    const int d   = tid >> 2;          // 0..63
    const int tp0 = (tid & 3) * 8;     // 0..24
#pragma unroll
    for (int j = 0; j < 8; j++) {
        const int tp = tp0 + j;
        unsigned h, l;
        split2(sv[2 * tp][d], sv[2 * tp + 1][d], h, l);
        const size_t o = ((size_t)bh * DH + d) * (T_SEQ / 2) + (t0 >> 1) + tp;
        g_Vth[o] = h; g_Vtl[o] = l;
    }
}

// ---------------------------------------------------------------------------
// Tensor-core GEMM v3: R6 loop structure (single-buffer, plain LDG/STS),
// operands pre-split -> staging is a pure uint4 copy, zero conversion.
// Block 128x128x32, 8 warps (2x4), warp tile 64x32. 3-MMA bf16 split.
// ---------------------------------------------------------------------------
template<bool SCATTER>
__global__ __launch_bounds__(256, 2)
void mma_gemm3(const unsigned* __restrict__ Ah, const unsigned* __restrict__ Al,
               const unsigned* __restrict__ Bh, const unsigned* __restrict__ Bl,
               const float* __restrict__ bias, float* __restrict__ out)
{
    __shared__ unsigned Ahi[128*20], Alo[128*20], Bhi[128*20], Blo[128*20];

    const int tid  = threadIdx.x;
    const int lane = tid & 31;
    const int warp = tid >> 5;
    const int wm   = warp >> 2;
    const int wn   = warp & 3;
    const int g    = lane >> 2;
    const int t    = lane & 3;
    const int m0   = blockIdx.y * 128;
    const int n0   = blockIdx.x * 128;

    float acc[4][4][4];
#pragma unroll
    for (int mt = 0; mt < 4; mt++)
#pragma unroll
        for (int nt = 0; nt < 4; nt++)
#pragma unroll
            for (int i = 0; i < 4; i++) acc[mt][nt][i] = 0.f;

    const int cr = tid >> 1;           // row 0..127
    const int ch = (tid & 1) * 8;      // word offset 0/8

    for (int i = 0; i < 32; i++) {
        const size_t as = (size_t)(m0 + cr) * KW + i * 16 + ch;
        const size_t bs = (size_t)(n0 + cr) * KW + i * 16 + ch;
        uint4 a0 = *(const uint4*)&Ah[as];
        uint4 a1 = *(const uint4*)&Ah[as + 4];
        uint4 a2 = *(const uint4*)&Al[as];
        uint4 a3 = *(const uint4*)&Al[as + 4];
        uint4 b0 = *(const uint4*)&Bh[bs];
        uint4 b1 = *(const uint4*)&Bh[bs + 4];
        uint4 b2 = *(const uint4*)&Bl[bs];
        uint4 b3 = *(const uint4*)&Bl[bs + 4];
        __syncthreads();               // previous tile fully consumed
        const int w = cr * 20 + ch;
        *(uint4*)&Ahi[w] = a0; *(uint4*)&Ahi[w + 4] = a1;
        *(uint4*)&Alo[w] = a2; *(uint4*)&Alo[w + 4] = a3;
        *(uint4*)&Bhi[w] = b0; *(uint4*)&Bhi[w + 4] = b1;
        *(uint4*)&Blo[w] = b2; *(uint4*)&Blo[w + 4] = b3;
        __syncthreads();

#pragma unroll
        for (int ks = 0; ks < 2; ks++) {
            unsigned ah[4][4], al[4][4], bh[4][2], bl[4][2];
#pragma unroll
            for (int mt = 0; mt < 4; mt++) {
                const int base = (wm * 64 + mt * 16 + g) * 20 + ks * 8 + t;
                ah[mt][0] = Ahi[base];       ah[mt][1] = Ahi[base + 160];
                ah[mt][2] = Ahi[base + 4];   ah[mt][3] = Ahi[base + 164];
                al[mt][0] = Alo[base];       al[mt][1] = Alo[base + 160];
                al[mt][2] = Alo[base + 4];   al[mt][3] = Alo[base + 164];
            }
#pragma unroll
            for (int nt = 0; nt < 4; nt++) {
                const int base = (wn * 32 + nt * 8 + g) * 20 + ks * 8 + t;
                bh[nt][0] = Bhi[base];       bh[nt][1] = Bhi[base + 4];
                bl[nt][0] = Blo[base];       bl[nt][1] = Blo[base + 4];
            }
#pragma unroll
            for (int mt = 0; mt < 4; mt++)
#pragma unroll
                for (int nt = 0; nt < 4; nt++) {
                    mma16816(acc[mt][nt], ah[mt][0], ah[mt][1], ah[mt][2], ah[mt][3],
                             bh[nt][0], bh[nt][1]);
                    mma16816(acc[mt][nt], ah[mt][0], ah[mt][1], ah[mt][2], ah[mt][3],
                             bl[nt][0], bl[nt][1]);
                    mma16816(acc[mt][nt], al[mt][0], al[mt][1], al[mt][2], al[mt][3],
                             bh[nt][0], bh[nt][1]);
                }
        }
    }

    // ---- epilogue ----
#pragma unroll
    for (int mt = 0; mt < 4; mt++) {
        const int mrow0 = m0 + wm * 64 + mt * 16 + g;
#pragma unroll
        for (int nt = 0; nt < 4; nt++) {
            const int c = n0 + wn * 32 + nt * 8 + 2 * t;
            const float b0 = bias[c], b1 = bias[c + 1];
            const float v00 = acc[mt][nt][0] + b0;
            const float v01 = acc[mt][nt][1] + b1;
            const float v10 = acc[mt][nt][2] + b0;
            const float v11 = acc[mt][nt][3] + b1;
            if (SCATTER) {
                const int which = c >> 10;                 // 0=Q 1=K 2=V
                const int cc = c & (DM - 1);
                const int h  = cc >> 6;
                const int d  = cc & (DH - 1);              // even
#pragma unroll
                for (int rr = 0; rr < 2; rr++) {
                    const int m   = mrow0 + rr * 8;
                    const int bb  = m >> 11;
                    const int tok = m & (T_SEQ - 1);
                    const size_t row = (size_t)(bb * NH + h) * T_SEQ + tok;
                    const float a = rr ? v10 : v00;
                    const float b = rr ? v11 : v01;
                    if (which == 0) {               // Q pre-scaled 1/sqrt(Dh)
                        unsigned h_, l_;
                        split2(a * 0.125f, b * 0.125f, h_, l_);
                        g_Qh[row * 32 + (d >> 1)] = h_;
                        g_Ql[row * 32 + (d >> 1)] = l_;
                    } else if (which == 1) {        // K
                        unsigned h_, l_;
                        split2(a, b, h_, l_);
                        g_Kh[row * 32 + (d >> 1)] = h_;
                        g_Kl[row * 32 + (d >> 1)] = l_;
                    } else {                        // V fp32
                        *(float2*)&g_V[row * DH + d] = make_float2(a, b);
                    }
                }
            } else {
                *(float2*)&out[(size_t)mrow0 * DM + c]       = make_float2(v00, v01);
                *(float2*)&out[(size_t)(mrow0 + 8) * DM + c] = make_float2(v10, v11);
            }
        }
    }
}

// ---------------------------------------------------------------------------
// Attention v4: R6 structure (64-row Q tiles, 4 warps), but Q/K/V all staged
// as pre-split uint4 copies (no conversion in the loop). P stays in registers
// (S C-frag == P A-frag). smem stride 36 words -> conflict-free fragment LDS.
// ---------------------------------------------------------------------------
#define ASTR 36
__global__ __launch_bounds__(128)
void attn_mma4()
{
    extern __shared__ unsigned smu[];
    unsigned* sQh = smu;
    unsigned* sQl = smu + 64 * ASTR;
    unsigned* sKh = smu + 2 * 64 * ASTR;
    unsigned* sKl = smu + 3 * 64 * ASTR;
    unsigned* sVh = smu + 4 * 64 * ASTR;   // [d][keypair]
    unsigned* sVl = smu + 5 * 64 * ASTR;

    const int tid  = threadIdx.x;
    const int lane = tid & 31;
    const int w    = tid >> 5;      // warp 0..3, rows 16w..16w+15
    const int g    = lane >> 2;
    const int t    = lane & 3;
    const int qt   = (int)(gridDim.x - 1) - (int)blockIdx.x;  // longest first
    const int bh   = blockIdx.y;
    const int q0   = qt * 64;

    const unsigned* Qh = g_Qh + (size_t)bh * T_SEQ * 32;
    const unsigned* Ql = g_Ql + (size_t)bh * T_SEQ * 32;
    const unsigned* Kh = g_Kh + (size_t)bh * T_SEQ * 32;
    const unsigned* Kl = g_Kl + (size_t)bh * T_SEQ * 32;
    const unsigned* Vth = g_Vth + (size_t)bh * DH * (T_SEQ / 2);
    const unsigned* Vtl = g_Vtl + (size_t)bh * DH * (T_SEQ / 2);

    const int sr   = tid >> 1;          // staging row 0..63
    const int sh   = (tid & 1) * 16;    // staging word offset 0/16

    // ---- stage Q once (pure copy) ----
    {
        const size_t src = (size_t)(q0 + sr) * 32 + sh;
        const int dst = sr * ASTR + sh;
#pragma unroll
        for (int j = 0; j < 4; j++) {
            *(uint4*)&sQh[dst + 4 * j] = *(const uint4*)&Qh[src + 4 * j];
            *(uint4*)&sQl[dst + 4 * j] = *(const uint4*)&Ql[src + 4 * j];
        }
    }

    float oacc[8][4];
#pragma unroll
    for (int nf = 0; nf < 8; nf++)
#pragma unroll
        for (int i = 0; i < 4; i++) oacc[nf][i] = 0.f;
    float mrun0 = -INFINITY, mrun1 = -INFINITY;
    float lrun0 = 0.f, lrun1 = 0.f;

    for (int kt = 0; kt <= qt; kt++) {
        __syncthreads();   // Q visible (iter 0) / prior frag reads done
        const int k0 = kt * 64;

        // ---- stage K (pure copy) ----
        {
            const size_t src = (size_t)(k0 + sr) * 32 + sh;
            const int dst = sr * ASTR + sh;
#pragma unroll
            for (int j = 0; j < 4; j++) {
                *(uint4*)&sKh[dst + 4 * j] = *(const uint4*)&Kh[src + 4 * j];
                *(uint4*)&sKl[dst + 4 * j] = *(const uint4*)&Kl[src + 4 * j];
            }
        }
        // ---- stage V transposed (pure copy; rows are d, words are tpairs) ----
        {
            const size_t src = (size_t)sr * (T_SEQ / 2) + kt * 32 + sh;
            const int dst = sr * ASTR + sh;
#pragma unroll
            for (int j = 0; j < 4; j++) {
                *(uint4*)&sVh[dst + 4 * j] = *(const uint4*)&Vth[src + 4 * j];
                *(uint4*)&sVl[dst + 4 * j] = *(const uint4*)&Vtl[src + 4 * j];
            }
        }
        __syncthreads();

        // ---- S = Q K^T ----
        float sacc[8][4];
#pragma unroll
        for (int nf = 0; nf < 8; nf++)
#pragma unroll
            for (int i = 0; i < 4; i++) sacc[nf][i] = 0.f;

#pragma unroll
        for (int ks = 0; ks < 4; ks++) {
            const int qb = (16 * w + g) * ASTR + ks * 8 + t;
            const unsigned qh0 = sQh[qb],     qh1 = sQh[qb + 8 * ASTR];
            const unsigned qh2 = sQh[qb + 4], qh3 = sQh[qb + 8 * ASTR + 4];
            const unsigned ql0 = sQl[qb],     ql1 = sQl[qb + 8 * ASTR];
            const unsigned ql2 = sQl[qb + 4], ql3 = sQl[qb + 8 * ASTR + 4];
#pragma unroll
            for (int nf = 0; nf < 8; nf++) {
                const int kb = (8 * nf + g) * ASTR + ks * 8 + t;
                const unsigned kh0 = sKh[kb], kh1 = sKh[kb + 4];
                const unsigned kl0 = sKl[kb], kl1 = sKl[kb + 4];
                mma16816(sacc[nf], qh0, qh1, qh2, qh3, kh0, kh1);
                mma16816(sacc[nf], qh0, qh1, qh2, qh3, kl0, kl1);
                mma16816(sacc[nf], ql0, ql1, ql2, ql3, kh0, kh1);
            }
        }

        // ---- causal mask on the diagonal tile ----
        if (kt == qt) {
            const int r0 = 16 * w + g, r1 = r0 + 8;
#pragma unroll
            for (int nf = 0; nf < 8; nf++) {
                const int c = 8 * nf + 2 * t;
                if (c     > r0) sacc[nf][0] = -INFINITY;
                if (c + 1 > r0) sacc[nf][1] = -INFINITY;
                if (c     > r1) sacc[nf][2] = -INFINITY;
                if (c + 1 > r1) sacc[nf][3] = -INFINITY;
            }
        }

        // ---- online softmax ----
        float rm0 = -INFINITY, rm1 = -INFINITY;
#pragma unroll
        for (int nf = 0; nf < 8; nf++) {
            rm0 = fmaxf(rm0, fmaxf(sacc[nf][0], sacc[nf][1]));
            rm1 = fmaxf(rm1, fmaxf(sacc[nf][2], sacc[nf][3]));
        }
        rm0 = fmaxf(rm0, __shfl_xor_sync(0xffffffffu, rm0, 1));
        rm0 = fmaxf(rm0, __shfl_xor_sync(0xffffffffu, rm0, 2));
        rm1 = fmaxf(rm1, __shfl_xor_sync(0xffffffffu, rm1, 1));
        rm1 = fmaxf(rm1, __shfl_xor_sync(0xffffffffu, rm1, 2));

        const float mn0 = fmaxf(mrun0, rm0);
        const float mn1 = fmaxf(mrun1, rm1);
        const float c0  = __expf(mrun0 - mn0);
        const float c1  = __expf(mrun1 - mn1);

        float rs0 = 0.f, rs1 = 0.f;
#pragma unroll
        for (int nf = 0; nf < 8; nf++) {
            sacc[nf][0] = __expf(sacc[nf][0] - mn0); rs0 += sacc[nf][0];
            sacc[nf][1] = __expf(sacc[nf][1] - mn0); rs0 += sacc[nf][1];
            sacc[nf][2] = __expf(sacc[nf][2] - mn1); rs1 += sacc[nf][2];
            sacc[nf][3] = __expf(sacc[nf][3] - mn1); rs1 += sacc[nf][3];
        }
        rs0 += __shfl_xor_sync(0xffffffffu, rs0, 1);
        rs0 += __shfl_xor_sync(0xffffffffu, rs0, 2);
        rs1 += __shfl_xor_sync(0xffffffffu, rs1, 1);
        rs1 += __shfl_xor_sync(0xffffffffu, rs1, 2);

        lrun0 = lrun0 * c0 + rs0;
        lrun1 = lrun1 * c1 + rs1;
        mrun0 = mn0;
        mrun1 = mn1;
#pragma unroll
        for (int nf = 0; nf < 8; nf++) {
            oacc[nf][0] *= c0; oacc[nf][1] *= c0;
            oacc[nf][2] *= c1; oacc[nf][3] *= c1;
        }

        // ---- O += P V (S C-frags ARE P A-frags) ----
#pragma unroll
        for (int ks = 0; ks < 4; ks++) {
            unsigned ph0, pl0, ph1, pl1, ph2, pl2, ph3, pl3;
            split2(sacc[2 * ks][0],     sacc[2 * ks][1],     ph0, pl0);
            split2(sacc[2 * ks][2],     sacc[2 * ks][3],     ph1, pl1);
            split2(sacc[2 * ks + 1][0], sacc[2 * ks + 1][1], ph2, pl2);
            split2(sacc[2 * ks + 1][2], sacc[2 * ks + 1][3], ph3, pl3);
#pragma unroll
            for (int nf = 0; nf < 8; nf++) {
                const int vb = (8 * nf + g) * ASTR + ks * 8 + t;
                const unsigned vh0 = sVh[vb], vh1 = sVh[vb + 4];
                const unsigned vl0 = sVl[vb], vl1 = sVl[vb + 4];
                mma16816(oacc[nf], ph0, ph1, ph2, ph3, vh0, vh1);
                mma16816(oacc[nf], ph0, ph1, ph2, ph3, vl0, vl1);
                mma16816(oacc[nf], pl0, pl1, pl2, pl3, vh0, vh1);
            }
        }
    }

    // ---- normalize; write pre-split to g_Ah/g_Al ----
    const float inv0 = 1.f / lrun0;
    const float inv1 = 1.f / lrun1;
    const int b  = bh >> 4;
    const int h  = bh & 15;
    const int r0 = q0 + 16 * w + g;
    const int r1 = r0 + 8;
#pragma unroll
    for (int nf = 0; nf < 8; nf++) {
        const int widx = h * 32 + 4 * nf + t;   // (h*64 + 8nf + 2t)/2
        unsigned hw, lw;
        split2(oacc[nf][0] * inv0, oacc[nf][1] * inv0, hw, lw);
        g_Ah[(size_t)(b * T_SEQ + r0) * KW + widx] = hw;
        g_Al[(size_t)(b * T_SEQ + r0) * KW + widx] = lw;
        split2(oacc[nf][2] * inv1, oacc[nf][3] * inv1, hw, lw);
        g_Ah[(size_t)(b * T_SEQ + r1) * KW + widx] = hw;
        g_Al[(size_t)(b * T_SEQ + r1) * KW + widx] = lw;
    }
}

// ---------------------------------------------------------------------------
extern "C" void kernel_launch(void* const* d_in, const int* in_sizes, int n_in,
                              void* d_out, int out_size)
{
    const float* x      = (const float*)d_in[0];
    const float* W_qkv  = (const float*)d_in[1];
    const float* b_qkv  = (const float*)d_in[2];
    const float* W_proj = (const float*)d_in[3];
    const float* b_proj = (const float*)d_in[4];
    float* out = (float*)d_out;

    (void)in_sizes; (void)n_in; (void)out_size;

    unsigned *Xh, *Xl, *Wqh, *Wql, *Wph, *Wpl, *Ah, *Al;
    cudaGetSymbolAddress((void**)&Xh,  g_Xh);
    cudaGetSymbolAddress((void**)&Xl,  g_Xl);
    cudaGetSymbolAddress((void**)&Wqh, g_Wqh);
    cudaGetSymbolAddress((void**)&Wql, g_Wql);
    cudaGetSymbolAddress((void**)&Wph, g_Wph);
    cudaGetSymbolAddress((void**)&Wpl, g_Wpl);
    cudaGetSymbolAddress((void**)&Ah,  g_Ah);
    cudaGetSymbolAddress((void**)&Al,  g_Al);

    const int attn_smem = 6 * 64 * ASTR * 4;   // 55296 B
    cudaFuncSetAttribute(attn_mma4,
                         cudaFuncAttributeMaxDynamicSharedMemorySize, attn_smem);

    // prep: split X; transpose+split both W
    split_rows_kernel<<<MROWS * KW / (256 * 4), 256>>>(x, Xh, Xl);
    dim3 gw1(DM / 64, N_QKV / 64);
    wsplit_kernel<<<gw1, 256>>>(W_qkv, Wqh, Wql, N_QKV);
    dim3 gw2(DM / 64, DM / 64);
    wsplit_kernel<<<gw2, 256>>>(W_proj, Wph, Wpl, DM);

    dim3 gA(N_QKV / 128, MROWS / 128);   // (24, 32)
    mma_gemm3<true><<<gA, 256>>>(Xh, Xl, Wqh, Wql, b_qkv, nullptr);

    // V transpose+split
    dim3 gV(T_SEQ / 64, BATCH * NH);
    vtrans_kernel<<<gV, 256>>>();

    dim3 gB(T_SEQ / 64, BATCH * NH);     // (32, 32)
    attn_mma4<<<gB, 128, attn_smem>>>();

    dim3 gC(DM / 128, MROWS / 128);      // (8, 32)
    mma_gemm3<false><<<gC, 256>>>(Ah, Al, Wph, Wpl, b_proj, out);
}

// round 11
// speedup vs baseline: 1.1788x; 1.1788x over previous
#include <cuda_runtime.h>
#include <cuda_bf16.h>
#include <math.h>

#define T_SEQ   2048
#define BATCH   2
#define DM      1024
#define NH      16
#define DH      64
#define MROWS   (BATCH*T_SEQ)    /* 4096 */
#define N_QKV   (3*DM)           /* 3072 */

// Scratch (allocation-free rule: __device__ globals). 64 MB total.
__device__ float g_Q[MROWS*DM];
__device__ float g_K[MROWS*DM];
__device__ float g_V[MROWS*DM];
__device__ float g_attn[MROWS*DM];

// ---------------------------------------------------------------------------
// bf16 split helpers: x = hi + lo with |x - hi - lo| ~ 2^-18 |x|.
// pack two (even, odd) bf16 into one 32-bit fragment word (low = even).
// ---------------------------------------------------------------------------
__device__ __forceinline__ void split2(float a, float b, unsigned &hi, unsigned &lo)
{
    __nv_bfloat16 ha = __float2bfloat16_rn(a);
    __nv_bfloat16 hb = __float2bfloat16_rn(b);
    __nv_bfloat162 h; h.x = ha; h.y = hb;
    hi = *reinterpret_cast<unsigned*>(&h);
    __nv_bfloat162 l = __floats2bfloat162_rn(a - __bfloat162float(ha),
                                             b - __bfloat162float(hb));
    lo = *reinterpret_cast<unsigned*>(&l);
}

__device__ __forceinline__ void mma16816(float* d,
    unsigned a0, unsigned a1, unsigned a2, unsigned a3,
    unsigned b0, unsigned b1)
{
    asm volatile(
        "mma.sync.aligned.m16n8k16.row.col.f32.bf16.bf16.f32 "
        "{%0,%1,%2,%3}, {%4,%5,%6,%7}, {%8,%9}, {%0,%1,%2,%3};\n"
        : "+f"(d[0]), "+f"(d[1]), "+f"(d[2]), "+f"(d[3])
        : "r"(a0), "r"(a1), "r"(a2), "r"(a3), "r"(b0), "r"(b1));
}

// ---------------------------------------------------------------------------
// Tensor-core GEMM (R6 recipe + double-buffer, ONE sync per k-iter).
// A[4096,1024] @ W[1024,NCOLS] + bias. Block 128x128x32, 8 warps (2x4),
// warp tile 64x32 = 4x4 m16n8k16 fragments. bf16 hi/lo split, 3 MMAs/frag.
// Staging keeps R6's fp32 LDG + split2 (the ALU chains hide load latency);
// double-buffered smem lets one warp's staging overlap others' MMAs.
// smem: 2 buffers x (Ahi|Alo|Bhi|Blo) x 128*20 words = 81920 B.
// ---------------------------------------------------------------------------
template<int NCOLS, bool SCATTER>
__global__ __launch_bounds__(256, 2)
void mma_gemm_db(const float* __restrict__ Ain, const float* __restrict__ W,
                 const float* __restrict__ bias, float* __restrict__ out)
{
    extern __shared__ unsigned sg[];

    const float* __restrict__ A = SCATTER ? Ain : (const float*)g_attn;

    const int tid  = threadIdx.x;
    const int lane = tid & 31;
    const int warp = tid >> 5;
    const int wm   = warp >> 2;     // 0..1
    const int wn   = warp & 3;      // 0..3
    const int g    = lane >> 2;     // 0..7
    const int t    = lane & 3;      // 0..3
    const int m0   = blockIdx.y * 128;
    const int n0   = blockIdx.x * 128;

    float acc[4][4][4];
#pragma unroll
    for (int mt = 0; mt < 4; mt++)
#pragma unroll
        for (int nt = 0; nt < 4; nt++)
#pragma unroll
            for (int i = 0; i < 4; i++) acc[mt][nt][i] = 0.f;

    const int ar  = tid >> 3;          // A row 0..31 (step 32)
    const int ak  = (tid & 7) << 2;    // A k offset
    const int bn  = tid & 127;         // B column (n)
    const int bk0 = (tid >> 7) << 2;   // 0 or 4

    for (int i = 0; i < 32; i++) {
        unsigned* Ahi = sg + (i & 1) * 10240;
        unsigned* Alo = Ahi + 2560;
        unsigned* Bhi = Ahi + 5120;
        unsigned* Blo = Ahi + 7680;
        const int k0 = i * 32;

        // ---- stage A (fp32 load + split; no preceding sync needed:
        //      this buffer was last read in compute(i-2), fenced by sync(i-1))
#pragma unroll
        for (int ii = 0; ii < 4; ii++) {
            const int r = ar + ii * 32;
            float4 v = *(const float4*)&A[(size_t)(m0 + r) * DM + k0 + ak];
            unsigned h0, l0, h1, l1;
            split2(v.x, v.y, h0, l0);
            split2(v.z, v.w, h1, l1);
            const int w = r * 20 + (ak >> 1);
            Ahi[w] = h0; Ahi[w + 1] = h1;
            Alo[w] = l0; Alo[w + 1] = l1;
        }
        // ---- stage B (transposed gathers; coalesced along n) ----
#pragma unroll
        for (int gi = 0; gi < 4; gi++) {
            const int k = bk0 + gi * 8;
            const float* p = &W[(size_t)(k0 + k) * NCOLS + n0 + bn];
            const float x0 = p[0];
            const float x1 = p[NCOLS];
            const float x2 = p[2 * NCOLS];
            const float x3 = p[3 * NCOLS];
            unsigned h0, l0, h1, l1;
            split2(x0, x1, h0, l0);
            split2(x2, x3, h1, l1);
            const int w = bn * 20 + (k >> 1);
            Bhi[w] = h0; Bhi[w + 1] = h1;
            Blo[w] = l0; Blo[w + 1] = l1;
        }
        __syncthreads();   // the ONLY sync: staging(i) visible to all

        // ---- compute: 2 k16-steps, 4x4 fragments, 3 MMAs each ----
#pragma unroll
        for (int ks = 0; ks < 2; ks++) {
            unsigned ah[4][4], al[4][4], bh[4][2], bl[4][2];
#pragma unroll
            for (int mt = 0; mt < 4; mt++) {
                const int base = (wm * 64 + mt * 16 + g) * 20 + ks * 8 + t;
                ah[mt][0] = Ahi[base];       ah[mt][1] = Ahi[base + 160];
                ah[mt][2] = Ahi[base + 4];   ah[mt][3] = Ahi[base + 164];
                al[mt][0] = Alo[base];       al[mt][1] = Alo[base + 160];
                al[mt][2] = Alo[base + 4];   al[mt][3] = Alo[base + 164];
            }
#pragma unroll
            for (int nt = 0; nt < 4; nt++) {
                const int base = (wn * 32 + nt * 8 + g) * 20 + ks * 8 + t;
                bh[nt][0] = Bhi[base];       bh[nt][1] = Bhi[base + 4];
                bl[nt][0] = Blo[base];       bl[nt][1] = Blo[base + 4];
            }
#pragma unroll
            for (int mt = 0; mt < 4; mt++)
#pragma unroll
                for (int nt = 0; nt < 4; nt++) {
                    mma16816(acc[mt][nt], ah[mt][0], ah[mt][1], ah[mt][2], ah[mt][3],
                             bh[nt][0], bh[nt][1]);
                    mma16816(acc[mt][nt], ah[mt][0], ah[mt][1], ah[mt][2], ah[mt][3],
                             bl[nt][0], bl[nt][1]);
                    mma16816(acc[mt][nt], al[mt][0], al[mt][1], al[mt][2], al[mt][3],
                             bh[nt][0], bh[nt][1]);
                }
        }
    }

    // ---- epilogue (R6): scatter Q/K/V fp32 head-major, or proj output ----
#pragma unroll
    for (int mt = 0; mt < 4; mt++) {
        const int mrow0 = m0 + wm * 64 + mt * 16 + g;
#pragma unroll
        for (int nt = 0; nt < 4; nt++) {
            const int c = n0 + wn * 32 + nt * 8 + 2 * t;
            const float b0 = bias[c], b1 = bias[c + 1];
            const float v00 = acc[mt][nt][0] + b0;
            const float v01 = acc[mt][nt][1] + b1;
            const float v10 = acc[mt][nt][2] + b0;
            const float v11 = acc[mt][nt][3] + b1;
            if (SCATTER) {
                const int which = c >> 10;
                const int cc = c & (DM - 1);
                const int h  = cc >> 6;
                const int d  = cc & (DH - 1);
                float* dst = (which == 0) ? g_Q : (which == 1) ? g_K : g_V;
#pragma unroll
                for (int rr = 0; rr < 2; rr++) {
                    const int m   = mrow0 + rr * 8;
                    const int bb  = m >> 11;
                    const int tok = m & (T_SEQ - 1);
                    const size_t idx = ((size_t)(bb * NH + h) * T_SEQ + tok) * DH + d;
                    *(float2*)&dst[idx] = rr ? make_float2(v10, v11)
                                             : make_float2(v00, v01);
                }
            } else {
                *(float2*)&out[(size_t)mrow0 * DM + c]       = make_float2(v00, v01);
                *(float2*)&out[(size_t)(mrow0 + 8) * DM + c] = make_float2(v10, v11);
            }
        }
    }
}

// ---------------------------------------------------------------------------
// Attention (R6 verbatim): causal flash attention on tensor cores.
// CTA = 64 query rows x one (b,h); 4 warps, warp owns 16 rows.
// S = (Q*0.125) K^T via bf16 hi/lo split (3 MMAs); online softmax in regs;
// P reuses S's C-fragment layout as the A-fragment of P.V (no smem for P);
// V staged transposed [d][key] so B-fragments load conflict-free.
// ---------------------------------------------------------------------------
#define ASTR 36
__global__ __launch_bounds__(128)
void attn_mma_kernel()
{
    extern __shared__ unsigned smu[];
    unsigned* sQh = smu;
    unsigned* sQl = smu + 64 * ASTR;
    unsigned* sKh = smu + 2 * 64 * ASTR;
    unsigned* sKl = smu + 3 * 64 * ASTR;
    unsigned* sVh = smu + 4 * 64 * ASTR;   // transposed: [d][keypair]
    unsigned* sVl = smu + 5 * 64 * ASTR;

    const int tid  = threadIdx.x;
    const int lane = tid & 31;
    const int w    = tid >> 5;      // warp 0..3, rows 16w..16w+15
    const int g    = lane >> 2;     // 0..7
    const int t    = lane & 3;      // 0..3
    const int qt   = (int)(gridDim.x - 1) - (int)blockIdx.x;  // longest first
    const int bh   = blockIdx.y;
    const int q0   = qt * 64;

    const float* Qg = g_Q + (size_t)bh * T_SEQ * DH;
    const float* Kg = g_K + (size_t)bh * T_SEQ * DH;
    const float* Vg = g_V + (size_t)bh * T_SEQ * DH;

    // ---- stage Q once, pre-scaled by 1/sqrt(Dh) ----
#pragma unroll
    for (int i = 0; i < 8; i++) {
        const int idx = tid + i * 128;
        const int row = idx >> 4;
        const int dq  = (idx & 15) << 2;
        float4 v = *(const float4*)&Qg[(q0 + row) * DH + dq];
        unsigned h0, l0, h1, l1;
        split2(v.x * 0.125f, v.y * 0.125f, h0, l0);
        split2(v.z * 0.125f, v.w * 0.125f, h1, l1);
        const int wo = row * ASTR + (dq >> 1);
        sQh[wo] = h0; sQh[wo + 1] = h1;
        sQl[wo] = l0; sQl[wo + 1] = l1;
    }

    float oacc[8][4];
#pragma unroll
    for (int nf = 0; nf < 8; nf++)
#pragma unroll
        for (int i = 0; i < 4; i++) oacc[nf][i] = 0.f;
    float mrun0 = -INFINITY, mrun1 = -INFINITY;
    float lrun0 = 0.f, lrun1 = 0.f;

    for (int kt = 0; kt <= qt; kt++) {
        __syncthreads();   // Q visible (iter 0) / prior frag reads done
        const int k0 = kt * 64;

        // ---- stage K natural [key][d] ----
#pragma unroll
        for (int i = 0; i < 8; i++) {
            const int idx = tid + i * 128;
            const int row = idx >> 4;
            const int dq  = (idx & 15) << 2;
            float4 v = *(const float4*)&Kg[(k0 + row) * DH + dq];
            unsigned h0, l0, h1, l1;
            split2(v.x, v.y, h0, l0);
            split2(v.z, v.w, h1, l1);
            const int wo = row * ASTR + (dq >> 1);
            sKh[wo] = h0; sKh[wo + 1] = h1;
            sKl[wo] = l0; sKl[wo + 1] = l1;
        }
        // ---- stage V transposed [d][keypair] (pairs along key) ----
#pragma unroll
        for (int i = 0; i < 4; i++) {
            const int r = tid & 31;                       // key pair 0..31
            const int d = (((tid >> 5) + (i << 2)) << 2); // d chunk
            const float* p0 = &Vg[(k0 + 2 * r) * DH + d];
            float4 v0 = *(const float4*)p0;
            float4 v1 = *(const float4*)(p0 + DH);
            unsigned h, l;
            split2(v0.x, v1.x, h, l); sVh[(d + 0) * ASTR + r] = h; sVl[(d + 0) * ASTR + r] = l;
            split2(v0.y, v1.y, h, l); sVh[(d + 1) * ASTR + r] = h; sVl[(d + 1) * ASTR + r] = l;
            split2(v0.z, v1.z, h, l); sVh[(d + 2) * ASTR + r] = h; sVl[(d + 2) * ASTR + r] = l;
            split2(v0.w, v1.w, h, l); sVh[(d + 3) * ASTR + r] = h; sVl[(d + 3) * ASTR + r] = l;
        }
        __syncthreads();

        // ---- S = Q K^T : 8 n-frags x 4 k-steps x 3 MMAs ----
        float sacc[8][4];
#pragma unroll
        for (int nf = 0; nf < 8; nf++)
#pragma unroll
            for (int i = 0; i < 4; i++) sacc[nf][i] = 0.f;

#pragma unroll
        for (int ks = 0; ks < 4; ks++) {
            const int qb = (16 * w + g) * ASTR + ks * 8 + t;
            const unsigned qh0 = sQh[qb],     qh1 = sQh[qb + 8 * ASTR];
            const unsigned qh2 = sQh[qb + 4], qh3 = sQh[qb + 8 * ASTR + 4];
            const unsigned ql0 = sQl[qb],     ql1 = sQl[qb + 8 * ASTR];
            const unsigned ql2 = sQl[qb + 4], ql3 = sQl[qb + 8 * ASTR + 4];
#pragma unroll
            for (int nf = 0; nf < 8; nf++) {
                const int kb = (8 * nf + g) * ASTR + ks * 8 + t;
                const unsigned kh0 = sKh[kb], kh1 = sKh[kb + 4];
                const unsigned kl0 = sKl[kb], kl1 = sKl[kb + 4];
                mma16816(sacc[nf], qh0, qh1, qh2, qh3, kh0, kh1);
                mma16816(sacc[nf], qh0, qh1, qh2, qh3, kl0, kl1);
                mma16816(sacc[nf], ql0, ql1, ql2, ql3, kh0, kh1);
            }
        }

        // ---- causal mask on the diagonal tile ----
        if (kt == qt) {
            const int r0 = 16 * w + g, r1 = r0 + 8;
#pragma unroll
            for (int nf = 0; nf < 8; nf++) {
                const int c = 8 * nf + 2 * t;
                if (c     > r0) sacc[nf][0] = -INFINITY;
                if (c + 1 > r0) sacc[nf][1] = -INFINITY;
                if (c     > r1) sacc[nf][2] = -INFINITY;
                if (c + 1 > r1) sacc[nf][3] = -INFINITY;
            }
        }

        // ---- online softmax (rows g, g+8; lanes sharing a row = t group) ----
        float rm0 = -INFINITY, rm1 = -INFINITY;
#pragma unroll
        for (int nf = 0; nf < 8; nf++) {
            rm0 = fmaxf(rm0, fmaxf(sacc[nf][0], sacc[nf][1]));
            rm1 = fmaxf(rm1, fmaxf(sacc[nf][2], sacc[nf][3]));
        }
        rm0 = fmaxf(rm0, __shfl_xor_sync(0xffffffffu, rm0, 1));
        rm0 = fmaxf(rm0, __shfl_xor_sync(0xffffffffu, rm0, 2));
        rm1 = fmaxf(rm1, __shfl_xor_sync(0xffffffffu, rm1, 1));
        rm1 = fmaxf(rm1, __shfl_xor_sync(0xffffffffu, rm1, 2));

        const float mn0 = fmaxf(mrun0, rm0);
        const float mn1 = fmaxf(mrun1, rm1);
        const float c0  = __expf(mrun0 - mn0);
        const float c1  = __expf(mrun1 - mn1);

        float rs0 = 0.f, rs1 = 0.f;
#pragma unroll
        for (int nf = 0; nf < 8; nf++) {
            sacc[nf][0] = __expf(sacc[nf][0] - mn0); rs0 += sacc[nf][0];
            sacc[nf][1] = __expf(sacc[nf][1] - mn0); rs0 += sacc[nf][1];
            sacc[nf][2] = __expf(sacc[nf][2] - mn1); rs1 += sacc[nf][2];
            sacc[nf][3] = __expf(sacc[nf][3] - mn1); rs1 += sacc[nf][3];
        }
        rs0 += __shfl_xor_sync(0xffffffffu, rs0, 1);
        rs0 += __shfl_xor_sync(0xffffffffu, rs0, 2);
        rs1 += __shfl_xor_sync(0xffffffffu, rs1, 1);
        rs1 += __shfl_xor_sync(0xffffffffu, rs1, 2);

        lrun0 = lrun0 * c0 + rs0;
        lrun1 = lrun1 * c1 + rs1;
        mrun0 = mn0;
        mrun1 = mn1;
#pragma unroll
        for (int nf = 0; nf < 8; nf++) {
            oacc[nf][0] *= c0; oacc[nf][1] *= c0;
            oacc[nf][2] *= c1; oacc[nf][3] *= c1;
        }

        // ---- O += P V : S's C-fragments ARE P's A-fragments ----
#pragma unroll
        for (int ks = 0; ks < 4; ks++) {
            unsigned ph0, pl0, ph1, pl1, ph2, pl2, ph3, pl3;
            split2(sacc[2 * ks][0],     sacc[2 * ks][1],     ph0, pl0);
            split2(sacc[2 * ks][2],     sacc[2 * ks][3],     ph1, pl1);
            split2(sacc[2 * ks + 1][0], sacc[2 * ks + 1][1], ph2, pl2);
            split2(sacc[2 * ks + 1][2], sacc[2 * ks + 1][3], ph3, pl3);
#pragma unroll
            for (int nf = 0; nf < 8; nf++) {
                const int vb = (8 * nf + g) * ASTR + ks * 8 + t;
                const unsigned vh0 = sVh[vb], vh1 = sVh[vb + 4];
                const unsigned vl0 = sVl[vb], vl1 = sVl[vb + 4];
                mma16816(oacc[nf], ph0, ph1, ph2, ph3, vh0, vh1);
                mma16816(oacc[nf], ph0, ph1, ph2, ph3, vl0, vl1);
                mma16816(oacc[nf], pl0, pl1, pl2, pl3, vh0, vh1);
            }
        }
    }

    // ---- normalize and write to g_attn in [B,T,C] (C = h*64 + d) ----
    const float inv0 = 1.f / lrun0;
    const float inv1 = 1.f / lrun1;
    const int b  = bh >> 4;
    const int h  = bh & 15;
    const int r0 = q0 + 16 * w + g;
    const int r1 = r0 + 8;
#pragma unroll
    for (int nf = 0; nf < 8; nf++) {
        const int c = h * DH + 8 * nf + 2 * t;
        *(float2*)&g_attn[(size_t)(b * T_SEQ + r0) * DM + c] =
            make_float2(oacc[nf][0] * inv0, oacc[nf][1] * inv0);
        *(float2*)&g_attn[(size_t)(b * T_SEQ + r1) * DM + c] =
            make_float2(oacc[nf][2] * inv1, oacc[nf][3] * inv1);
    }
}

// ---------------------------------------------------------------------------
extern "C" void kernel_launch(void* const* d_in, const int* in_sizes, int n_in,
                              void* d_out, int out_size)
{
    const float* x      = (const float*)d_in[0];
    const float* W_qkv  = (const float*)d_in[1];
    const float* b_qkv  = (const float*)d_in[2];
    const float* W_proj = (const float*)d_in[3];
    const float* b_proj = (const float*)d_in[4];
    float* out = (float*)d_out;

    (void)in_sizes; (void)n_in; (void)out_size;

    const int gemm_smem = 2 * 4 * 128 * 20 * 4;   // 81920 B
    const int attn_smem = 6 * 64 * ASTR * 4;      // 55296 B
    cudaFuncSetAttribute(mma_gemm_db<N_QKV, true>,
                         cudaFuncAttributeMaxDynamicSharedMemorySize, gemm_smem);
    cudaFuncSetAttribute(mma_gemm_db<DM, false>,
                         cudaFuncAttributeMaxDynamicSharedMemorySize, gemm_smem);
    cudaFuncSetAttribute(attn_mma_kernel,
                         cudaFuncAttributeMaxDynamicSharedMemorySize, attn_smem);

    dim3 gA(N_QKV / 128, MROWS / 128);   // (24, 32)
    mma_gemm_db<N_QKV, true><<<gA, 256, gemm_smem>>>(x, W_qkv, b_qkv, nullptr);

    dim3 gB(T_SEQ / 64, BATCH * NH);     // (32, 32)
    attn_mma_kernel<<<gB, 128, attn_smem>>>();

    dim3 gC(DM / 128, MROWS / 128);      // (8, 32)
    mma_gemm_db<DM, false><<<gC, 256, gemm_smem>>>(nullptr, W_proj, b_proj, out);
}